// round 17
// baseline (speedup 1.0000x reference)
#include <cuda_runtime.h>
#include <cuda_bf16.h>
#include <mma.h>
#include <math.h>

using namespace nvcuda;

// ---------------- problem constants ----------------
#define B_    512
#define L_    64
#define DDYN_ 16
#define DSTAT_ 8
#define H_    512
#define C_    1024
#define KTOP_ 16
#define P_    8
#define NB_   50000
#define CAP_  96
#define OVF_  4096
#define TEMP_ 0.2f

// ---------------- device scratch ----------------
__device__ float g_local[B_ * H_];
__device__ float g_query[B_ * H_];     // UNNORMALIZED query
__device__ float g_qinv[B_];           // 1 / max(||q||, eps)
__device__ float g_sim[B_ * C_];
__device__ float g_fused2[B_ * H_];
__device__ int   g_cnt[NB_];
__device__ int   g_slot[NB_ * CAP_];
__device__ int   g_ovf[OVF_];
__device__ int   g_ovf_cnt;

// bf16 hi/lo splits (weights + activations)
__device__ __nv_bfloat16 g_Wqh[H_ * H_],      g_Wql[H_ * H_];
__device__ __nv_bfloat16 g_Wtrh[2 * H_ * H_], g_Wtrl[2 * H_ * H_];
__device__ __nv_bfloat16 g_Wgh[3 * H_ * H_],  g_Wgl[3 * H_ * H_];
__device__ __nv_bfloat16 g_Woh[H_ * H_],      g_Wol[H_ * H_];
__device__ __nv_bfloat16 g_localh[B_ * H_],   g_locall[B_ * H_];
__device__ __nv_bfloat16 g_donorh[B_ * H_],   g_donorl[B_ * H_];
__device__ __nv_bfloat16 g_protoh[B_ * H_],   g_protol[B_ * H_];
__device__ __nv_bfloat16 g_fusedh[B_ * H_],   g_fusedl[B_ * H_];

__device__ __forceinline__ void split_store(float v, __nv_bfloat16* dh, __nv_bfloat16* dl, int i)
{
    __nv_bfloat16 h = __float2bfloat16(v);
    dh[i] = h;
    dl[i] = __float2bfloat16(v - __bfloat162float(h));
}

// ---------------- weight split: fp32 -> (hi, lo) bf16 ----------------
__global__ void split_weights(const float* __restrict__ Wq, const float* __restrict__ Wtr,
                              const float* __restrict__ Wg, const float* __restrict__ Wo)
{
    const int NQ = H_ * H_, NTR = 2 * H_ * H_, NG = 3 * H_ * H_;
    int i = blockIdx.x * 256 + threadIdx.x;
    if (i >= 7 * H_ * H_) return;
    float v; __nv_bfloat16 *dh, *dl; int off;
    if (i < NQ)                 { v = Wq[i];                 dh = g_Wqh;  dl = g_Wql;  off = i; }
    else if (i < NQ + NTR)      { off = i - NQ;              v = Wtr[off]; dh = g_Wtrh; dl = g_Wtrl; }
    else if (i < NQ + NTR + NG) { off = i - NQ - NTR;        v = Wg[off];  dh = g_Wgh;  dl = g_Wgl; }
    else                        { off = i - NQ - NTR - NG;   v = Wo[off];  dh = g_Woh;  dl = g_Wol; }
    split_store(v, dh, dl, off);
}

// ---------------- encoder (writes fp32 local + bf16 splits) ----------------
__global__ void encode_kernel(const float* __restrict__ seq,
                              const float* __restrict__ mask,
                              const float* __restrict__ stat,
                              const float* __restrict__ W_seq,
                              const float* __restrict__ W_stat,
                              const float* __restrict__ b_enc)
{
    int b = blockIdx.x;
    int tid = threadIdx.x;       // 512 threads
    __shared__ float pooled[DDYN_];
    __shared__ float sv[DSTAT_];
    __shared__ float msum;

    if (tid < DDYN_) {
        float s = 0.f;
        for (int l = 0; l < L_; l++)
            s += seq[(b * L_ + l) * DDYN_ + tid] * mask[b * L_ + l];
        pooled[tid] = s;
    }
    if (tid == 31) {
        float ms = 0.f;
        for (int l = 0; l < L_; l++) ms += mask[b * L_ + l];
        msum = ms;
    }
    if (tid >= 32 && tid < 32 + DSTAT_) sv[tid - 32] = stat[b * DSTAT_ + (tid - 32)];
    __syncthreads();
    if (tid < DDYN_) pooled[tid] = pooled[tid] / fmaxf(msum, 1e-6f);
    __syncthreads();

    float acc = b_enc[tid];
    #pragma unroll
    for (int d = 0; d < DDYN_; d++) acc += pooled[d] * W_seq[d * H_ + tid];
    #pragma unroll
    for (int s = 0; s < DSTAT_; s++) acc += sv[s] * W_stat[s * H_ + tid];
    float r = fmaxf(acc, 0.f);
    int o = b * H_ + tid;
    g_local[o] = r;
    split_store(r, g_localh, g_locall, o);
}

// ======== bf16 3-split tensor-core GEMM: C = A@W + bias (EPI 1: relu) ========
// CTA tile M32 x N64, 128 threads (4 warps, 2x2), wmma 16x16x16, K-tile 32.
template<int EPI>
__global__ __launch_bounds__(128) void gemm_mma(const __nv_bfloat16* __restrict__ Ah,
                                                const __nv_bfloat16* __restrict__ Al,
                                                int K,
                                                const __nv_bfloat16* __restrict__ Wh,
                                                const __nv_bfloat16* __restrict__ Wl,
                                                const float* __restrict__ bias,
                                                float* __restrict__ C)
{
    __shared__ __align__(16) __nv_bfloat16 sAh[32][40], sAl[32][40];
    __shared__ __align__(16) __nv_bfloat16 sWh[32][72], sWl[32][72];
    __shared__ __align__(16) float sC[32][72];

    int tid = threadIdx.x;
    int warp = tid >> 5;
    int wm = warp >> 1, wn = warp & 1;
    int bm = blockIdx.y * 32, bn = blockIdx.x * 64;
    int ar = tid >> 2, ac = (tid & 3) * 8;

    wmma::fragment<wmma::accumulator, 16, 16, 16, float> acc[2];
    wmma::fill_fragment(acc[0], 0.f);
    wmma::fill_fragment(acc[1], 0.f);

    for (int kt = 0; kt < K / 32; kt++) {
        *(uint4*)&sAh[ar][ac] = *(const uint4*)&Ah[(bm + ar) * K + kt * 32 + ac];
        *(uint4*)&sAl[ar][ac] = *(const uint4*)&Al[(bm + ar) * K + kt * 32 + ac];
        #pragma unroll
        for (int i = 0; i < 2; i++) {
            int u = tid * 2 + i;
            int wr = u >> 3, wc = (u & 7) * 8;
            *(uint4*)&sWh[wr][wc] = *(const uint4*)&Wh[(kt * 32 + wr) * H_ + bn + wc];
            *(uint4*)&sWl[wr][wc] = *(const uint4*)&Wl[(kt * 32 + wr) * H_ + bn + wc];
        }
        __syncthreads();
        #pragma unroll
        for (int ks = 0; ks < 2; ks++) {
            wmma::fragment<wmma::matrix_a, 16, 16, 16, __nv_bfloat16, wmma::row_major> fah, fal;
            wmma::load_matrix_sync(fah, &sAh[wm * 16][ks * 16], 40);
            wmma::load_matrix_sync(fal, &sAl[wm * 16][ks * 16], 40);
            #pragma unroll
            for (int nf = 0; nf < 2; nf++) {
                wmma::fragment<wmma::matrix_b, 16, 16, 16, __nv_bfloat16, wmma::row_major> fbh, fbl;
                wmma::load_matrix_sync(fbh, &sWh[ks * 16][wn * 32 + nf * 16], 72);
                wmma::load_matrix_sync(fbl, &sWl[ks * 16][wn * 32 + nf * 16], 72);
                wmma::mma_sync(acc[nf], fah, fbh, acc[nf]);
                wmma::mma_sync(acc[nf], fah, fbl, acc[nf]);
                wmma::mma_sync(acc[nf], fal, fbh, acc[nf]);
            }
        }
        __syncthreads();
    }

    wmma::store_matrix_sync(&sC[wm * 16][wn * 32],      acc[0], 72, wmma::mem_row_major);
    wmma::store_matrix_sync(&sC[wm * 16][wn * 32 + 16], acc[1], 72, wmma::mem_row_major);
    __syncthreads();
    #pragma unroll
    for (int i = 0; i < 16; i++) {
        int idx = tid * 16 + i;
        int r = idx >> 6, n = idx & 63;
        float v = sC[r][n] + bias[bn + n];
        if (EPI == 1) v = fmaxf(v, 0.f);
        C[(bm + r) * H_ + bn + n] = v;
    }
}

// ==== fused transfer+gate+fuse on tensor cores; writes fused bf16 splits ====
__global__ __launch_bounds__(128) void gemm_tg_mma(
    const float* __restrict__ localf,
    const __nv_bfloat16* __restrict__ Lh, const __nv_bfloat16* __restrict__ Ll,
    const __nv_bfloat16* __restrict__ Dh, const __nv_bfloat16* __restrict__ Dl,
    const __nv_bfloat16* __restrict__ Ph, const __nv_bfloat16* __restrict__ Pl,
    const __nv_bfloat16* __restrict__ WGh, const __nv_bfloat16* __restrict__ WGl,
    const __nv_bfloat16* __restrict__ WTh, const __nv_bfloat16* __restrict__ WTl,
    const float* __restrict__ b_tr, const float* __restrict__ b_gate,
    __nv_bfloat16* __restrict__ Fh, __nv_bfloat16* __restrict__ Fl)
{
    __shared__ __align__(16) __nv_bfloat16 sAh[32][40], sAl[32][40];
    __shared__ __align__(16) __nv_bfloat16 sGh[32][72], sGl[32][72];
    __shared__ __align__(16) __nv_bfloat16 sTh[32][72], sTl[32][72];
    __shared__ __align__(16) float sC[32][72];

    int tid = threadIdx.x;
    int warp = tid >> 5;
    int wm = warp >> 1, wn = warp & 1;
    int bm = blockIdx.y * 32, bn = blockIdx.x * 64;
    int ar = tid >> 2, ac = (tid & 3) * 8;

    wmma::fragment<wmma::accumulator, 16, 16, 16, float> accG[2], accT[2];
    wmma::fill_fragment(accG[0], 0.f); wmma::fill_fragment(accG[1], 0.f);
    wmma::fill_fragment(accT[0], 0.f); wmma::fill_fragment(accT[1], 0.f);

    for (int kt = 0; kt < 48; kt++) {
        int seg = kt >> 4;
        const __nv_bfloat16* Ah = (seg == 0) ? Lh : ((seg == 1) ? Dh : Ph);
        const __nv_bfloat16* Al = (seg == 0) ? Ll : ((seg == 1) ? Dl : Pl);
        int koff = (kt & 15) * 32;
        bool has_t = (seg >= 1);

        *(uint4*)&sAh[ar][ac] = *(const uint4*)&Ah[(bm + ar) * H_ + koff + ac];
        *(uint4*)&sAl[ar][ac] = *(const uint4*)&Al[(bm + ar) * H_ + koff + ac];
        #pragma unroll
        for (int i = 0; i < 2; i++) {
            int u = tid * 2 + i;
            int wr = u >> 3, wc = (u & 7) * 8;
            *(uint4*)&sGh[wr][wc] = *(const uint4*)&WGh[(kt * 32 + wr) * H_ + bn + wc];
            *(uint4*)&sGl[wr][wc] = *(const uint4*)&WGl[(kt * 32 + wr) * H_ + bn + wc];
            if (has_t) {
                int ktr = (kt - 16) * 32 + wr;
                *(uint4*)&sTh[wr][wc] = *(const uint4*)&WTh[ktr * H_ + bn + wc];
                *(uint4*)&sTl[wr][wc] = *(const uint4*)&WTl[ktr * H_ + bn + wc];
            }
        }
        __syncthreads();
        #pragma unroll
        for (int ks = 0; ks < 2; ks++) {
            wmma::fragment<wmma::matrix_a, 16, 16, 16, __nv_bfloat16, wmma::row_major> fah, fal;
            wmma::load_matrix_sync(fah, &sAh[wm * 16][ks * 16], 40);
            wmma::load_matrix_sync(fal, &sAl[wm * 16][ks * 16], 40);
            #pragma unroll
            for (int nf = 0; nf < 2; nf++) {
                wmma::fragment<wmma::matrix_b, 16, 16, 16, __nv_bfloat16, wmma::row_major> fbh, fbl;
                wmma::load_matrix_sync(fbh, &sGh[ks * 16][wn * 32 + nf * 16], 72);
                wmma::load_matrix_sync(fbl, &sGl[ks * 16][wn * 32 + nf * 16], 72);
                wmma::mma_sync(accG[nf], fah, fbh, accG[nf]);
                wmma::mma_sync(accG[nf], fah, fbl, accG[nf]);
                wmma::mma_sync(accG[nf], fal, fbh, accG[nf]);
                if (has_t) {
                    wmma::fragment<wmma::matrix_b, 16, 16, 16, __nv_bfloat16, wmma::row_major> tbh, tbl;
                    wmma::load_matrix_sync(tbh, &sTh[ks * 16][wn * 32 + nf * 16], 72);
                    wmma::load_matrix_sync(tbl, &sTl[ks * 16][wn * 32 + nf * 16], 72);
                    wmma::mma_sync(accT[nf], fah, tbh, accT[nf]);
                    wmma::mma_sync(accT[nf], fah, tbl, accT[nf]);
                    wmma::mma_sync(accT[nf], fal, tbh, accT[nf]);
                }
            }
        }
        __syncthreads();
    }

    // epilogue: gate values first, then transfer values
    float gv[16];
    wmma::store_matrix_sync(&sC[wm * 16][wn * 32],      accG[0], 72, wmma::mem_row_major);
    wmma::store_matrix_sync(&sC[wm * 16][wn * 32 + 16], accG[1], 72, wmma::mem_row_major);
    __syncthreads();
    #pragma unroll
    for (int i = 0; i < 16; i++) {
        int idx = tid * 16 + i;
        int r = idx >> 6, n = idx & 63;
        gv[i] = sC[r][n] + b_gate[bn + n];
    }
    __syncthreads();
    wmma::store_matrix_sync(&sC[wm * 16][wn * 32],      accT[0], 72, wmma::mem_row_major);
    wmma::store_matrix_sync(&sC[wm * 16][wn * 32 + 16], accT[1], 72, wmma::mem_row_major);
    __syncthreads();
    #pragma unroll
    for (int i = 0; i < 16; i++) {
        int idx = tid * 16 + i;
        int r = idx >> 6, n = idx & 63;
        int o = (bm + r) * H_ + bn + n;
        float tr = fmaxf(sC[r][n] + b_tr[bn + n], 0.f);
        float g = 1.f / (1.f + expf(-gv[i]));
        float f = g * localf[o] + (1.f - g) * tr;
        split_store(f, Fh, Fl, o);
    }
}

// ---------------- prototype attention + query-norm (scale-invariance) -------
__global__ void proto_kernel(const float* __restrict__ protos)
{
    int b = blockIdx.x;
    int tid = threadIdx.x;   // 256
    int warp = tid >> 5, lane = tid & 31;
    __shared__ float q[H_];
    __shared__ float red[8];
    __shared__ float pw[P_];

    float v0 = g_query[b * H_ + tid];
    float v1 = g_query[b * H_ + 256 + tid];
    q[tid] = v0; q[256 + tid] = v1;
    float s = v0 * v0 + v1 * v1;
    #pragma unroll
    for (int o = 16; o > 0; o >>= 1) s += __shfl_down_sync(0xffffffffu, s, o);
    if (lane == 0) red[warp] = s;
    __syncthreads();
    if (tid == 0) {
        float t = 0.f;
        #pragma unroll
        for (int w = 0; w < 8; w++) t += red[w];
        float qi = 1.f / fmaxf(sqrtf(t), 1e-12f);
        red[0] = qi;
        g_qinv[b] = qi;
    }
    __syncthreads();
    float qinv = red[0];

    {
        float dot = 0.f, nrm = 0.f;
        for (int i = lane; i < H_; i += 32) {
            float p = protos[warp * H_ + i];
            dot += p * q[i];
            nrm += p * p;
        }
        #pragma unroll
        for (int o = 16; o > 0; o >>= 1) {
            dot += __shfl_down_sync(0xffffffffu, dot, o);
            nrm += __shfl_down_sync(0xffffffffu, nrm, o);
        }
        if (lane == 0) pw[warp] = dot * qinv / fmaxf(sqrtf(nrm), 1e-12f);
    }
    __syncthreads();
    if (tid == 0) {
        float m = pw[0];
        #pragma unroll
        for (int p = 1; p < P_; p++) m = fmaxf(m, pw[p]);
        float sum = 0.f;
        #pragma unroll
        for (int p = 0; p < P_; p++) { pw[p] = expf(pw[p] - m); sum += pw[p]; }
        float invs = 1.f / sum;
        #pragma unroll
        for (int p = 0; p < P_; p++) pw[p] *= invs;
    }
    __syncthreads();
    for (int h = tid; h < H_; h += 256) {
        float acc = 0.f;
        #pragma unroll
        for (int p = 0; p < P_; p++) acc += pw[p] * protos[p * H_ + h];
        split_store(acc, g_protoh, g_protol, b * H_ + h);
    }
}

// ============ sim via row-inversion: each bank row read ONCE ============

__global__ void sim_fill_kernel(const int* __restrict__ cand)
{
    int e = blockIdx.x * 256 + threadIdx.x;
    if (e >= B_ * C_) return;
    int idx = cand[e];
    int pos = atomicAdd(&g_cnt[idx], 1);
    if (pos < CAP_) {
        g_slot[idx * CAP_ + pos] = e;
    } else {
        int o = atomicAdd(&g_ovf_cnt, 1);
        if (o < OVF_) g_ovf[o] = e;
    }
}

__global__ void sim_rows_kernel(const float* __restrict__ bank_keys)
{
    int gw = (blockIdx.x * blockDim.x + threadIdx.x) >> 5;
    int lane = threadIdx.x & 31;
    if (gw >= NB_) return;

    int n = g_cnt[gw];
    if (n == 0) return;
    if (lane == 0) g_cnt[gw] = 0;
    if (n > CAP_) n = CAP_;

    const float4* row = (const float4*)(bank_keys + (size_t)gw * H_);
    float4 kr[4];
    #pragma unroll
    for (int p = 0; p < 4; p++) kr[p] = row[p * 32 + lane];

    const float4* q4 = (const float4*)g_query;
    int base = gw * CAP_;
    int j = 0;
    for (; j + 2 <= n; j += 2) {
        int e0 = g_slot[base + j];
        int e1 = g_slot[base + j + 1];
        int b0 = e0 >> 10, b1 = e1 >> 10;
        float4 q0[4], q1[4];
        #pragma unroll
        for (int p = 0; p < 4; p++) q0[p] = q4[b0 * 128 + p * 32 + lane];
        #pragma unroll
        for (int p = 0; p < 4; p++) q1[p] = q4[b1 * 128 + p * 32 + lane];
        float a0 = 0.f, a1 = 0.f;
        #pragma unroll
        for (int p = 0; p < 4; p++) {
            a0 += kr[p].x * q0[p].x + kr[p].y * q0[p].y + kr[p].z * q0[p].z + kr[p].w * q0[p].w;
            a1 += kr[p].x * q1[p].x + kr[p].y * q1[p].y + kr[p].z * q1[p].z + kr[p].w * q1[p].w;
        }
        #pragma unroll
        for (int o = 16; o > 0; o >>= 1) {
            a0 += __shfl_xor_sync(0xffffffffu, a0, o);
            a1 += __shfl_xor_sync(0xffffffffu, a1, o);
        }
        if (lane == 0) {
            g_sim[e0] = a0;
            g_sim[e1] = a1;
        }
    }
    if (j < n) {
        int e0 = g_slot[base + j];
        int b0 = e0 >> 10;
        float a0 = 0.f;
        #pragma unroll
        for (int p = 0; p < 4; p++) {
            float4 q0 = q4[b0 * 128 + p * 32 + lane];
            a0 += kr[p].x * q0.x + kr[p].y * q0.y + kr[p].z * q0.z + kr[p].w * q0.w;
        }
        #pragma unroll
        for (int o = 16; o > 0; o >>= 1)
            a0 += __shfl_xor_sync(0xffffffffu, a0, o);
        if (lane == 0) g_sim[e0] = a0;
    }
}

__global__ void sim_fixup_kernel(const float* __restrict__ bank_keys,
                                 const int* __restrict__ cand)
{
    __shared__ int n;
    if (threadIdx.x == 0) n = g_ovf_cnt;
    __syncthreads();
    int nn = n; if (nn > OVF_) nn = OVF_;
    for (int i = threadIdx.x; i < nn; i += 256) {
        int e = g_ovf[i];
        int b = e >> 10;
        int idx = cand[e];
        const float* row = bank_keys + (size_t)idx * H_;
        const float* q = g_query + b * H_;
        float acc = 0.f;
        for (int h = 0; h < H_; h++) acc += row[h] * q[h];
        g_sim[e] = acc;
    }
    __syncthreads();
    if (threadIdx.x == 0) g_ovf_cnt = 0;
}

// ---------------- top-16 + softmax (qinv-scaled) + donor gather (splits) -------
__global__ void topk_donor_kernel(const int* __restrict__ cand,
                                  const float* __restrict__ bank_values)
{
    int b = blockIdx.x;
    int tid = threadIdx.x;   // 256
    int warp = tid >> 5, lane = tid & 31;
    __shared__ float s[C_];
    __shared__ float wv[8];
    __shared__ int   wi[8];
    __shared__ float topv[KTOP_];
    __shared__ float topw[KTOP_];
    __shared__ int   topg[KTOP_];

    for (int i = tid; i < C_; i += 256) s[i] = g_sim[b * C_ + i];
    __syncthreads();

    for (int it = 0; it < KTOP_; it++) {
        float bv = -1e30f; int bi = 0x7fffffff;
        #pragma unroll
        for (int r = 0; r < C_ / 256; r++) {
            int i = tid + r * 256;
            float v = s[i];
            if (v > bv || (v == bv && i < bi)) { bv = v; bi = i; }
        }
        #pragma unroll
        for (int o = 16; o > 0; o >>= 1) {
            float ov = __shfl_down_sync(0xffffffffu, bv, o);
            int   oi = __shfl_down_sync(0xffffffffu, bi, o);
            if (ov > bv || (ov == bv && oi < bi)) { bv = ov; bi = oi; }
        }
        if (lane == 0) { wv[warp] = bv; wi[warp] = bi; }
        __syncthreads();
        if (tid == 0) {
            float mv = wv[0]; int mi = wi[0];
            #pragma unroll
            for (int w = 1; w < 8; w++) {
                if (wv[w] > mv || (wv[w] == mv && wi[w] < mi)) { mv = wv[w]; mi = wi[w]; }
            }
            topv[it] = mv;
            topg[it] = cand[b * C_ + mi];
            s[mi] = -1e30f;
        }
        __syncthreads();
    }

    if (tid == 0) {
        float qinv = g_qinv[b];
        float m = topv[0];
        float sum = 0.f;
        #pragma unroll
        for (int k = 0; k < KTOP_; k++) {
            float e = expf((topv[k] - m) * qinv / TEMP_);
            topw[k] = e; sum += e;
        }
        float inv = 1.f / sum;
        #pragma unroll
        for (int k = 0; k < KTOP_; k++) topw[k] *= inv;
    }
    __syncthreads();

    for (int h = tid; h < H_; h += 256) {
        float acc = 0.f;
        #pragma unroll
        for (int k = 0; k < KTOP_; k++)
            acc += topw[k] * bank_values[(size_t)topg[k] * H_ + h];
        split_store(acc, g_donorh, g_donorl, b * H_ + h);
    }
}

// ---------------- heads ----------------
__global__ void heads_kernel(const float* __restrict__ W_quant,
                             const float* __restrict__ b_quant,
                             const float* __restrict__ W_ev,
                             const float* __restrict__ b_ev,
                             float* __restrict__ out)
{
    int b = blockIdx.x;
    int tid = threadIdx.x;   // 256, 8 warps -> 8 outputs
    int warp = tid >> 5, lane = tid & 31;
    __shared__ float res[8];
    const float* x = g_fused2 + b * H_;

    float acc = 0.f;
    if (warp < 6) {
        int t = warp / 3, q = warp % 3;
        for (int h = lane; h < H_; h += 32)
            acc += x[h] * W_quant[(t * H_ + h) * 3 + q];
        #pragma unroll
        for (int o = 16; o > 0; o >>= 1) acc += __shfl_down_sync(0xffffffffu, acc, o);
        if (lane == 0) res[warp] = acc + b_quant[t * 3 + q];
    } else {
        int t = warp - 6;
        for (int h = lane; h < H_; h += 32)
            acc += x[h] * W_ev[t * H_ + h];
        #pragma unroll
        for (int o = 16; o > 0; o >>= 1) acc += __shfl_down_sync(0xffffffffu, acc, o);
        if (lane == 0) res[warp] = acc + b_ev[t];
    }
    __syncthreads();
    if (tid == 0) {
        #pragma unroll
        for (int t = 0; t < 2; t++) {
            float a = res[t * 3 + 0], c = res[t * 3 + 1], d = res[t * 3 + 2];
            float tmp;
            if (a > c) { tmp = a; a = c; c = tmp; }
            if (c > d) { tmp = c; c = d; d = tmp; }
            if (a > c) { tmp = a; a = c; c = tmp; }
            out[b * 8 + t * 3 + 0] = a;
            out[b * 8 + t * 3 + 1] = c;
            out[b * 8 + t * 3 + 2] = d;
        }
        out[b * 8 + 6] = res[6];
        out[b * 8 + 7] = res[7];
    }
}

// ---------------- launch ----------------
extern "C" void kernel_launch(void* const* d_in, const int* in_sizes, int n_in,
                              void* d_out, int out_size)
{
    const float* seq        = (const float*)d_in[0];
    const float* mask       = (const float*)d_in[1];
    const float* stat       = (const float*)d_in[2];
    const float* bank_keys  = (const float*)d_in[3];
    const float* bank_vals  = (const float*)d_in[4];
    const int*   cand       = (const int*)d_in[5];
    const float* W_seq      = (const float*)d_in[6];
    const float* W_stat     = (const float*)d_in[7];
    const float* b_enc      = (const float*)d_in[8];
    const float* W_q        = (const float*)d_in[9];
    const float* b_q        = (const float*)d_in[10];
    const float* protos     = (const float*)d_in[11];
    const float* W_tr       = (const float*)d_in[12];
    const float* b_tr       = (const float*)d_in[13];
    const float* W_gate     = (const float*)d_in[14];
    const float* b_gate     = (const float*)d_in[15];
    const float* W_out      = (const float*)d_in[16];
    const float* b_out      = (const float*)d_in[17];
    const float* W_quant    = (const float*)d_in[18];
    const float* b_quant    = (const float*)d_in[19];
    const float* W_ev       = (const float*)d_in[20];
    const float* b_ev       = (const float*)d_in[21];
    float* out = (float*)d_out;
    (void)in_sizes; (void)n_in; (void)out_size;

    static float *p_local = nullptr, *p_query = nullptr, *p_fused2 = nullptr;
    static __nv_bfloat16 *p_Wqh, *p_Wql, *p_Wtrh, *p_Wtrl, *p_Wgh, *p_Wgl, *p_Woh, *p_Wol;
    static __nv_bfloat16 *p_lh, *p_ll, *p_dh, *p_dl, *p_ph, *p_pl, *p_fh, *p_fl;
    if (!p_local) {
        cudaGetSymbolAddress((void**)&p_local,  g_local);
        cudaGetSymbolAddress((void**)&p_query,  g_query);
        cudaGetSymbolAddress((void**)&p_fused2, g_fused2);
        cudaGetSymbolAddress((void**)&p_Wqh,  g_Wqh);  cudaGetSymbolAddress((void**)&p_Wql,  g_Wql);
        cudaGetSymbolAddress((void**)&p_Wtrh, g_Wtrh); cudaGetSymbolAddress((void**)&p_Wtrl, g_Wtrl);
        cudaGetSymbolAddress((void**)&p_Wgh,  g_Wgh);  cudaGetSymbolAddress((void**)&p_Wgl,  g_Wgl);
        cudaGetSymbolAddress((void**)&p_Woh,  g_Woh);  cudaGetSymbolAddress((void**)&p_Wol,  g_Wol);
        cudaGetSymbolAddress((void**)&p_lh, g_localh); cudaGetSymbolAddress((void**)&p_ll, g_locall);
        cudaGetSymbolAddress((void**)&p_dh, g_donorh); cudaGetSymbolAddress((void**)&p_dl, g_donorl);
        cudaGetSymbolAddress((void**)&p_ph, g_protoh); cudaGetSymbolAddress((void**)&p_pl, g_protol);
        cudaGetSymbolAddress((void**)&p_fh, g_fusedh); cudaGetSymbolAddress((void**)&p_fl, g_fusedl);
    }

    dim3 ggrid(H_ / 64, B_ / 32);   // (8, 16) = 128 CTAs, 128 threads each

    // weight splits + candidate binning (independent of query path)
    split_weights<<<(7 * H_ * H_ + 255) / 256, 256>>>(W_q, W_tr, W_gate, W_out);
    sim_fill_kernel<<<(B_ * C_) / 256, 256>>>(cand);

    // encoder (+ local splits), query projection on tensor cores
    encode_kernel<<<B_, 512>>>(seq, mask, stat, W_seq, W_stat, b_enc);
    gemm_mma<0><<<ggrid, 128>>>(p_lh, p_ll, H_, p_Wqh, p_Wql, b_q, p_query);

    // prototype attention + qinv (writes proto splits)
    proto_kernel<<<B_, 256>>>(protos);

    // similarities: one pass over bank rows + tiny overflow fixup
    sim_rows_kernel<<<(NB_ * 32 + 255) / 256, 256>>>(bank_keys);
    sim_fixup_kernel<<<1, 256>>>(bank_keys, cand);

    // top-16 (qinv-scaled softmax) + donor (writes donor splits)
    topk_donor_kernel<<<B_, 256>>>(cand, bank_vals);

    // fused transfer+gate+fuse on tensor cores (writes fused splits)
    gemm_tg_mma<<<ggrid, 128>>>(p_local, p_lh, p_ll, p_dh, p_dl, p_ph, p_pl,
                                p_Wgh, p_Wgl, p_Wtrh, p_Wtrl, b_tr, b_gate, p_fh, p_fl);

    // output projection on tensor cores, heads
    gemm_mma<1><<<ggrid, 128>>>(p_fh, p_fl, H_, p_Woh, p_Wol, b_out, p_fused2);
    heads_kernel<<<B_, 256>>>(W_quant, b_quant, W_ev, b_ev, out);
}